// round 5
// baseline (speedup 1.0000x reference)
#include <cuda_runtime.h>
#include <cuda_bf16.h>
#include <cstdint>

#define N_NODES 50000
#define N_EDGES 600000
#define D_IN    256
#define D_OUT   128

// ---------------- scratch (static device globals; no allocation) ----------------
// split bf16 planes for all GEMM operands / activations
__device__ __nv_bfloat16 g_Ehi[N_NODES * D_IN],  g_Elo[N_NODES * D_IN];   // gathered embed
__device__ __nv_bfloat16 g_Xhi[N_NODES * D_OUT], g_Xlo[N_NODES * D_OUT]; // gemm1 out
__device__ __nv_bfloat16 g_Zhi[N_NODES * D_OUT], g_Zlo[N_NODES * D_OUT]; // agg out (1 & 2)
__device__ __nv_bfloat16 g_Hhi[N_NODES * D_OUT], g_Hlo[N_NODES * D_OUT]; // gemm2 out
__device__ __nv_bfloat16 g_Wnh[128 * D_IN],  g_Wnl[128 * D_IN];
__device__ __nv_bfloat16 g_w1h[128 * D_OUT], g_w1l[128 * D_OUT];
__device__ __nv_bfloat16 g_w2h[128 * D_OUT], g_w2l[128 * D_OUT];

__device__ float g_dinv[N_NODES];
__device__ int   g_deg [N_NODES];
__device__ int   g_cur [N_NODES];
__device__ int   g_off [N_NODES + 1];
__device__ int   g_bsum [256];
__device__ int   g_bbase[256];
__device__ int   g_csr [N_EDGES];

// ---------------- split helpers ----------------
__device__ __forceinline__ void split2(float x, float y, uint32_t& hi, uint32_t& lo) {
    __nv_bfloat162 h = __floats2bfloat162_rn(x, y);
    float2 hf = __bfloat1622float2(h);
    __nv_bfloat162 l = __floats2bfloat162_rn(x - hf.x, y - hf.y);
    hi = *(uint32_t*)&h; lo = *(uint32_t*)&l;
}
__device__ __forceinline__ void split4(float4 v, uint2& hi, uint2& lo) {
    split2(v.x, v.y, hi.x, lo.x);
    split2(v.z, v.w, hi.y, lo.y);
}

// ---------------- pre-split kernels ----------------
// gather embed rows by token and split into E planes
__global__ void k_presplit(const float* __restrict__ embed, const int* __restrict__ tokens) {
    int t = blockIdx.x * 256 + threadIdx.x;          // over N_NODES*64 float4s
    if (t >= N_NODES * (D_IN / 4)) return;
    int row = t >> 6, q = t & 63;
    int tok = __ldg(&tokens[row]);
    float4 v = ((const float4*)embed)[(size_t)tok * (D_IN / 4) + q];
    uint2 hi, lo; split4(v, hi, lo);
    ((uint2*)g_Ehi)[(size_t)row * (D_IN / 4) + q] = hi;
    ((uint2*)g_Elo)[(size_t)row * (D_IN / 4) + q] = lo;
}
// split all three weight matrices
__global__ void k_splitw(const float* __restrict__ Wn, const float* __restrict__ w1,
                         const float* __restrict__ w2) {
    int i = blockIdx.x * 256 + threadIdx.x;          // float4 index, 16384 total
    const float* src; __nv_bfloat16 *ph, *pl; int off;
    if (i < 8192)       { src = Wn; ph = g_Wnh; pl = g_Wnl; off = i; }
    else if (i < 12288) { src = w1; ph = g_w1h; pl = g_w1l; off = i - 8192; }
    else                { src = w2; ph = g_w2h; pl = g_w2l; off = i - 12288; }
    float4 v = ((const float4*)src)[off];
    uint2 hi, lo; split4(v, hi, lo);
    ((uint2*)ph)[off] = hi; ((uint2*)pl)[off] = lo;
}

// ---------------- graph-structure kernels ----------------
__global__ void k_zero() {
    int i = blockIdx.x * blockDim.x + threadIdx.x;
    if (i < N_NODES) { g_deg[i] = 0; g_cur[i] = 0; }
}
__global__ void k_count(const int* __restrict__ dst) {
    int e = blockIdx.x * blockDim.x + threadIdx.x;
    if (e < N_EDGES) atomicAdd(&g_deg[dst[e]], 1);
}
__global__ void k_scan1() {
    __shared__ int s[256];
    int i = blockIdx.x * 256 + threadIdx.x;
    int v = (i < N_NODES) ? g_deg[i] : 0;
    if (i < N_NODES) g_dinv[i] = rsqrtf((float)(v + 1));
    s[threadIdx.x] = v; __syncthreads();
    for (int d = 128; d > 0; d >>= 1) {
        if (threadIdx.x < d) s[threadIdx.x] += s[threadIdx.x + d];
        __syncthreads();
    }
    if (threadIdx.x == 0) g_bsum[blockIdx.x] = s[0];
}
__global__ void k_scan2(int nblk) {
    __shared__ int s[256];
    int t = threadIdx.x;
    int v = (t < nblk) ? g_bsum[t] : 0;
    s[t] = v; __syncthreads();
    for (int d = 1; d < 256; d <<= 1) {
        int u = (t >= d) ? s[t - d] : 0;
        __syncthreads(); s[t] += u; __syncthreads();
    }
    g_bbase[t] = s[t] - v;
    if (t == 0) g_off[N_NODES] = N_EDGES;
}
__global__ void k_scan3() {
    __shared__ int s[256];
    int t = threadIdx.x;
    int i = blockIdx.x * 256 + t;
    int v = (i < N_NODES) ? g_deg[i] : 0;
    s[t] = v; __syncthreads();
    for (int d = 1; d < 256; d <<= 1) {
        int u = (t >= d) ? s[t - d] : 0;
        __syncthreads(); s[t] += u; __syncthreads();
    }
    if (i < N_NODES) g_off[i] = g_bbase[blockIdx.x] + s[t] - v;
}
__global__ void k_fill(const int* __restrict__ src, const int* __restrict__ dst) {
    int e = blockIdx.x * blockDim.x + threadIdx.x;
    if (e < N_EDGES) {
        int d = dst[e];
        int pos = g_off[d] + atomicAdd(&g_cur[d], 1);
        g_csr[pos] = src[e];
    }
}

// ---------------- tensor-core GEMM (pre-split bf16 planes, fp32 accum) ----------------
// out[n][j] = sum_k A[n][k]*W[j][k] + bias[j]; optional relu; split or fp32 output.
// CTA 128x128, 256 thr, warps 4(M)x2(N), warp tile 32x64, 3-pass hi/lo MMA.
#define SROWW 20                       // smem row stride in u32 words (80B; conflict-free)

__device__ __forceinline__ void mma16816(float* d, uint32_t a0, uint32_t a1,
                                         uint32_t a2, uint32_t a3,
                                         uint32_t b0, uint32_t b1) {
    asm volatile(
        "mma.sync.aligned.m16n8k16.row.col.f32.bf16.bf16.f32 "
        "{%0,%1,%2,%3}, {%4,%5,%6,%7}, {%8,%9}, {%0,%1,%2,%3};"
        : "+f"(d[0]), "+f"(d[1]), "+f"(d[2]), "+f"(d[3])
        : "r"(a0), "r"(a1), "r"(a2), "r"(a3), "r"(b0), "r"(b1));
}

template<int K, bool RELU_OUT, bool SPLIT_OUT>
__global__ void __launch_bounds__(256)
k_gemm(const __nv_bfloat16* __restrict__ Ahi, const __nv_bfloat16* __restrict__ Alo,
       const __nv_bfloat16* __restrict__ Whi, const __nv_bfloat16* __restrict__ Wlo,
       const float* __restrict__ bias,
       __nv_bfloat16* __restrict__ Ohi, __nv_bfloat16* __restrict__ Olo,
       float* __restrict__ Of)
{
    __shared__ __align__(16) uint32_t sm[4 * 128 * SROWW];   // Ah, Al, Wh, Wl
    uint32_t* sAh = sm;
    uint32_t* sAl = sm + 128 * SROWW;
    uint32_t* sWh = sm + 2 * 128 * SROWW;
    uint32_t* sWl = sm + 3 * 128 * SROWW;

    const int tid  = threadIdx.x;
    const int wid  = tid >> 5;
    const int lane = tid & 31;
    const int m_base = (wid >> 1) * 32;
    const int n_base = (wid & 1) * 64;
    const int n0   = blockIdx.x * 128;
    const int qr = lane >> 2;
    const int qj = lane & 3;

    float acc[2][8][4];
    #pragma unroll
    for (int mt = 0; mt < 2; mt++)
        #pragma unroll
        for (int nt = 0; nt < 8; nt++)
            #pragma unroll
            for (int q = 0; q < 4; q++) acc[mt][nt][q] = 0.f;

    constexpr int K8  = K / 8;           // uint4 per row
    constexpr int NCH = K / 32;          // 32-col chunks

    for (int c = 0; c < NCH; c++) {
        // 4 planes x 128 rows x 4 uint4 = 2048 uint4 / 256 thr = 8 iters
        #pragma unroll
        for (int it = 0; it < 8; it++) {
            int i     = it * 256 + tid;
            int plane = i >> 9;
            int r     = (i >> 2) & 127;
            int q     = i & 3;
            const __nv_bfloat16* P = (plane == 0) ? Ahi : (plane == 1) ? Alo
                                   : (plane == 2) ? Whi : Wlo;
            int rg;
            if (plane < 2) { int node = n0 + r; if (node >= N_NODES) node = N_NODES - 1; rg = node; }
            else           rg = r;
            uint4 v = ((const uint4*)P)[(size_t)rg * K8 + c * 4 + q];
            *(uint4*)((char*)sm + plane * (128 * SROWW * 4) + r * (SROWW * 4) + q * 16) = v;
        }
        __syncthreads();

        #pragma unroll
        for (int ks = 0; ks < 2; ks++) {
            const int kw = ks * 8 + qj;
            uint32_t ah[2][4], al[2][4];
            #pragma unroll
            for (int mt = 0; mt < 2; mt++) {
                int r0 = (m_base + mt * 16 + qr) * SROWW;
                int r1 = (m_base + mt * 16 + qr + 8) * SROWW;
                ah[mt][0] = sAh[r0 + kw];     ah[mt][1] = sAh[r1 + kw];
                ah[mt][2] = sAh[r0 + kw + 4]; ah[mt][3] = sAh[r1 + kw + 4];
                al[mt][0] = sAl[r0 + kw];     al[mt][1] = sAl[r1 + kw];
                al[mt][2] = sAl[r0 + kw + 4]; al[mt][3] = sAl[r1 + kw + 4];
            }
            #pragma unroll
            for (int nt = 0; nt < 8; nt++) {
                int nr = (n_base + nt * 8 + qr) * SROWW;
                uint32_t bh0 = sWh[nr + kw], bh1 = sWh[nr + kw + 4];
                uint32_t bl0 = sWl[nr + kw], bl1 = sWl[nr + kw + 4];
                #pragma unroll
                for (int mt = 0; mt < 2; mt++) {
                    mma16816(acc[mt][nt], ah[mt][0], ah[mt][1], ah[mt][2], ah[mt][3], bh0, bh1);
                    mma16816(acc[mt][nt], ah[mt][0], ah[mt][1], ah[mt][2], ah[mt][3], bl0, bl1);
                    mma16816(acc[mt][nt], al[mt][0], al[mt][1], al[mt][2], al[mt][3], bh0, bh1);
                }
            }
        }
        __syncthreads();
    }

    // ---- epilogue ----
    #pragma unroll
    for (int mt = 0; mt < 2; mt++) {
        int r0 = n0 + m_base + mt * 16 + qr;
        int r1 = r0 + 8;
        #pragma unroll
        for (int nt = 0; nt < 8; nt++) {
            int col = n_base + nt * 8 + qj * 2;
            float b0 = bias[col], b1 = bias[col + 1];
            float vx0 = acc[mt][nt][0] + b0, vy0 = acc[mt][nt][1] + b1;
            float vx1 = acc[mt][nt][2] + b0, vy1 = acc[mt][nt][3] + b1;
            if (RELU_OUT) {
                vx0 = fmaxf(vx0, 0.f); vy0 = fmaxf(vy0, 0.f);
                vx1 = fmaxf(vx1, 0.f); vy1 = fmaxf(vy1, 0.f);
            }
            if (SPLIT_OUT) {
                uint32_t hi, lo;
                if (r0 < N_NODES) {
                    split2(vx0, vy0, hi, lo);
                    ((uint32_t*)Ohi)[(size_t)r0 * 64 + (col >> 1)] = hi;
                    ((uint32_t*)Olo)[(size_t)r0 * 64 + (col >> 1)] = lo;
                }
                if (r1 < N_NODES) {
                    split2(vx1, vy1, hi, lo);
                    ((uint32_t*)Ohi)[(size_t)r1 * 64 + (col >> 1)] = hi;
                    ((uint32_t*)Olo)[(size_t)r1 * 64 + (col >> 1)] = lo;
                }
            } else {
                if (r0 < N_NODES)
                    *(float2*)(Of + (size_t)r0 * D_OUT + col) = make_float2(vx0, vy0);
                if (r1 < N_NODES)
                    *(float2*)(Of + (size_t)r1 * D_OUT + col) = make_float2(vx1, vy1);
            }
        }
    }
}

// ---------------- normalized aggregation on split planes ----------------
// out[n] = dinv[n] * sum_{s in n ∪ in(n)} dinv[s] * x[s]
__device__ __forceinline__ void acc_row(float* a, uint2 h, uint2 l, float d) {
    float2 h0 = __bfloat1622float2(*(__nv_bfloat162*)&h.x);
    float2 h1 = __bfloat1622float2(*(__nv_bfloat162*)&h.y);
    float2 l0 = __bfloat1622float2(*(__nv_bfloat162*)&l.x);
    float2 l1 = __bfloat1622float2(*(__nv_bfloat162*)&l.y);
    a[0] = fmaf(h0.x + l0.x, d, a[0]);
    a[1] = fmaf(h0.y + l0.y, d, a[1]);
    a[2] = fmaf(h1.x + l1.x, d, a[2]);
    a[3] = fmaf(h1.y + l1.y, d, a[3]);
}

__global__ void k_agg(const __nv_bfloat16* __restrict__ xhi, const __nv_bfloat16* __restrict__ xlo,
                      __nv_bfloat16* __restrict__ ohi, __nv_bfloat16* __restrict__ olo)
{
    int gw   = (blockIdx.x * blockDim.x + threadIdx.x) >> 5;
    int lane = threadIdx.x & 31;
    if (gw >= N_NODES) return;

    const uint2* H = (const uint2*)xhi;
    const uint2* L = (const uint2*)xlo;
    float di = g_dinv[gw];

    float a[4] = {0.f, 0.f, 0.f, 0.f};
    acc_row(a, H[(size_t)gw * 32 + lane], L[(size_t)gw * 32 + lane], di);   // self

    int b = g_off[gw], e = g_off[gw + 1];
    int i = b;
    for (; i + 4 <= e; i += 4) {
        int s0 = g_csr[i], s1 = g_csr[i+1], s2 = g_csr[i+2], s3 = g_csr[i+3];
        float d0 = g_dinv[s0], d1 = g_dinv[s1], d2 = g_dinv[s2], d3 = g_dinv[s3];
        uint2 h0 = H[(size_t)s0 * 32 + lane], l0 = L[(size_t)s0 * 32 + lane];
        uint2 h1 = H[(size_t)s1 * 32 + lane], l1 = L[(size_t)s1 * 32 + lane];
        uint2 h2 = H[(size_t)s2 * 32 + lane], l2 = L[(size_t)s2 * 32 + lane];
        uint2 h3 = H[(size_t)s3 * 32 + lane], l3 = L[(size_t)s3 * 32 + lane];
        acc_row(a, h0, l0, d0); acc_row(a, h1, l1, d1);
        acc_row(a, h2, l2, d2); acc_row(a, h3, l3, d3);
    }
    for (; i < e; i++) {
        int s = g_csr[i];
        acc_row(a, H[(size_t)s * 32 + lane], L[(size_t)s * 32 + lane], g_dinv[s]);
    }

    uint2 hi, lo;
    split2(a[0] * di, a[1] * di, hi.x, lo.x);
    split2(a[2] * di, a[3] * di, hi.y, lo.y);
    ((uint2*)ohi)[(size_t)gw * 32 + lane] = hi;
    ((uint2*)olo)[(size_t)gw * 32 + lane] = lo;
}

// ---------------- launch ----------------
extern "C" void kernel_launch(void* const* d_in, const int* in_sizes, int n_in,
                              void* d_out, int out_size)
{
    const int*   tokens = (const int*)  d_in[0];
    const int*   eidx   = (const int*)  d_in[1];
    const float* embed  = (const float*)d_in[2];
    const float* Wn     = (const float*)d_in[3];
    const float* Wb     = (const float*)d_in[4];
    const float* w1     = (const float*)d_in[5];
    const float* b1     = (const float*)d_in[6];
    const float* w2     = (const float*)d_in[7];
    const float* b2     = (const float*)d_in[8];
    float* out = (float*)d_out;

    const int* src = eidx;
    const int* dst = eidx + N_EDGES;

    __nv_bfloat16 *Ehi, *Elo, *Xhi, *Xlo, *Zhi, *Zlo, *Hhi, *Hlo;
    __nv_bfloat16 *Wnh, *Wnl, *w1h, *w1l, *w2h, *w2l;
    cudaGetSymbolAddress((void**)&Ehi, g_Ehi); cudaGetSymbolAddress((void**)&Elo, g_Elo);
    cudaGetSymbolAddress((void**)&Xhi, g_Xhi); cudaGetSymbolAddress((void**)&Xlo, g_Xlo);
    cudaGetSymbolAddress((void**)&Zhi, g_Zhi); cudaGetSymbolAddress((void**)&Zlo, g_Zlo);
    cudaGetSymbolAddress((void**)&Hhi, g_Hhi); cudaGetSymbolAddress((void**)&Hlo, g_Hlo);
    cudaGetSymbolAddress((void**)&Wnh, g_Wnh); cudaGetSymbolAddress((void**)&Wnl, g_Wnl);
    cudaGetSymbolAddress((void**)&w1h, g_w1h); cudaGetSymbolAddress((void**)&w1l, g_w1l);
    cudaGetSymbolAddress((void**)&w2h, g_w2h); cudaGetSymbolAddress((void**)&w2l, g_w2l);

    const int NB_N = (N_NODES + 255) / 256;
    const int NB_E = (N_EDGES + 255) / 256;
    const int NB_G = (N_NODES + 127) / 128;
    const int NB_C = (N_NODES * 32 + 255) / 256;
    const int NB_P = (N_NODES * (D_IN / 4) + 255) / 256;

    // pre-split (independent of graph structure)
    k_presplit<<<NB_P, 256>>>(embed, tokens);
    k_splitw  <<<64,  256>>>(Wn, w1, w2);
    k_zero    <<<NB_N, 256>>>();
    // GEMM1: x' = gathered-embed @ Wn^T + Wb  (split out)   [index 3 — ncu slot]
    k_gemm<D_IN, false, true><<<NB_G, 256>>>(Ehi, Elo, Wnh, Wnl, Wb, Xhi, Xlo, nullptr);
    // graph structure
    k_count<<<NB_E, 256>>>(dst);
    k_scan1<<<NB_N, 256>>>();
    k_scan2<<<1,    256>>>(NB_N);
    k_scan3<<<NB_N, 256>>>();
    k_fill <<<NB_E, 256>>>(src, dst);
    // agg1: Z = D^-1/2 (A+I) D^-1/2 x'
    k_agg<<<NB_C, 256>>>(Xhi, Xlo, Zhi, Zlo);
    // GEMM2: H = relu(Z @ w1^T + b1)  (split out)
    k_gemm<D_OUT, true, true><<<NB_G, 256>>>(Zhi, Zlo, w1h, w1l, b1, Hhi, Hlo, nullptr);
    // agg2: Z = D^-1/2 (A+I) D^-1/2 H
    k_agg<<<NB_C, 256>>>(Hhi, Hlo, Zhi, Zlo);
    // GEMM3: out = Z @ w2^T + b2  (fp32 out)
    k_gemm<D_OUT, false, false><<<NB_G, 256>>>(Zhi, Zlo, w2h, w2l, b2, nullptr, nullptr, out);
}

// round 6
// speedup vs baseline: 1.3597x; 1.3597x over previous
#include <cuda_runtime.h>
#include <cuda_bf16.h>
#include <cstdint>

#define N_NODES 50000
#define N_EDGES 600000
#define D_IN    256
#define D_OUT   128

// ---------------- scratch (static device globals; no allocation) ----------------
__device__ __nv_bfloat16 g_Ehi[N_NODES * D_IN],  g_Elo[N_NODES * D_IN];   // gathered embed planes
__device__ __nv_bfloat16 g_Zhi[N_NODES * D_OUT], g_Zlo[N_NODES * D_OUT]; // agg output planes
__device__ float g_xf[N_NODES * D_OUT];   // gemm1 out (prescaled fp32)
__device__ float g_hf[N_NODES * D_OUT];   // gemm2 out (relu, prescaled fp32)
__device__ __nv_bfloat16 g_Wnh[128 * D_IN],  g_Wnl[128 * D_IN];
__device__ __nv_bfloat16 g_w1h[128 * D_OUT], g_w1l[128 * D_OUT];
__device__ __nv_bfloat16 g_w2h[128 * D_OUT], g_w2l[128 * D_OUT];

__device__ float g_dinv[N_NODES];
__device__ int   g_deg [N_NODES];
__device__ int   g_cur [N_NODES];
__device__ int   g_off [N_NODES + 1];
__device__ int   g_bsum [256];
__device__ int   g_bbase[256];
__device__ int   g_csr [N_EDGES];

// ---------------- helpers ----------------
__device__ __forceinline__ void split2(float x, float y, uint32_t& hi, uint32_t& lo) {
    __nv_bfloat162 h = __floats2bfloat162_rn(x, y);
    float2 hf = __bfloat1622float2(h);
    __nv_bfloat162 l = __floats2bfloat162_rn(x - hf.x, y - hf.y);
    hi = *(uint32_t*)&h; lo = *(uint32_t*)&l;
}
__device__ __forceinline__ void split4(float4 v, uint2& hi, uint2& lo) {
    split2(v.x, v.y, hi.x, lo.x);
    split2(v.z, v.w, hi.y, lo.y);
}
__device__ __forceinline__ void cp_async16(uint32_t saddr, const void* gaddr) {
    asm volatile("cp.async.cg.shared.global [%0], [%1], 16;" :: "r"(saddr), "l"(gaddr));
}
__device__ __forceinline__ void cp_commit() {
    asm volatile("cp.async.commit_group;" ::: "memory");
}
template<int N> __device__ __forceinline__ void cp_wait() {
    asm volatile("cp.async.wait_group %0;" :: "n"(N) : "memory");
}

// ---------------- pre-split kernels ----------------
__global__ void k_presplit(const float* __restrict__ embed, const int* __restrict__ tokens) {
    int t = blockIdx.x * 256 + threadIdx.x;
    if (t >= N_NODES * (D_IN / 4)) return;
    int row = t >> 6, q = t & 63;
    int tok = __ldg(&tokens[row]);
    float4 v = ((const float4*)embed)[(size_t)tok * (D_IN / 4) + q];
    uint2 hi, lo; split4(v, hi, lo);
    ((uint2*)g_Ehi)[(size_t)row * (D_IN / 4) + q] = hi;
    ((uint2*)g_Elo)[(size_t)row * (D_IN / 4) + q] = lo;
}
__global__ void k_splitw(const float* __restrict__ Wn, const float* __restrict__ w1,
                         const float* __restrict__ w2) {
    int i = blockIdx.x * 256 + threadIdx.x;
    const float* src; __nv_bfloat16 *ph, *pl; int off;
    if (i < 8192)       { src = Wn; ph = g_Wnh; pl = g_Wnl; off = i; }
    else if (i < 12288) { src = w1; ph = g_w1h; pl = g_w1l; off = i - 8192; }
    else                { src = w2; ph = g_w2h; pl = g_w2l; off = i - 12288; }
    float4 v = ((const float4*)src)[off];
    uint2 hi, lo; split4(v, hi, lo);
    ((uint2*)ph)[off] = hi; ((uint2*)pl)[off] = lo;
}

// ---------------- graph-structure kernels ----------------
__global__ void k_zero() {
    int i = blockIdx.x * blockDim.x + threadIdx.x;
    if (i < N_NODES) { g_deg[i] = 0; g_cur[i] = 0; }
}
__global__ void k_count(const int* __restrict__ dst) {
    int e = blockIdx.x * blockDim.x + threadIdx.x;
    if (e < N_EDGES) atomicAdd(&g_deg[dst[e]], 1);
}
__global__ void k_scan1() {
    __shared__ int s[256];
    int i = blockIdx.x * 256 + threadIdx.x;
    int v = (i < N_NODES) ? g_deg[i] : 0;
    if (i < N_NODES) g_dinv[i] = rsqrtf((float)(v + 1));
    s[threadIdx.x] = v; __syncthreads();
    for (int d = 128; d > 0; d >>= 1) {
        if (threadIdx.x < d) s[threadIdx.x] += s[threadIdx.x + d];
        __syncthreads();
    }
    if (threadIdx.x == 0) g_bsum[blockIdx.x] = s[0];
}
__global__ void k_scan2(int nblk) {
    __shared__ int s[256];
    int t = threadIdx.x;
    int v = (t < nblk) ? g_bsum[t] : 0;
    s[t] = v; __syncthreads();
    for (int d = 1; d < 256; d <<= 1) {
        int u = (t >= d) ? s[t - d] : 0;
        __syncthreads(); s[t] += u; __syncthreads();
    }
    g_bbase[t] = s[t] - v;
    if (t == 0) g_off[N_NODES] = N_EDGES;
}
__global__ void k_scan3() {
    __shared__ int s[256];
    int t = threadIdx.x;
    int i = blockIdx.x * 256 + t;
    int v = (i < N_NODES) ? g_deg[i] : 0;
    s[t] = v; __syncthreads();
    for (int d = 1; d < 256; d <<= 1) {
        int u = (t >= d) ? s[t - d] : 0;
        __syncthreads(); s[t] += u; __syncthreads();
    }
    if (i < N_NODES) g_off[i] = g_bbase[blockIdx.x] + s[t] - v;
}
__global__ void k_fill(const int* __restrict__ src, const int* __restrict__ dst) {
    int e = blockIdx.x * blockDim.x + threadIdx.x;
    if (e < N_EDGES) {
        int d = dst[e];
        int pos = g_off[d] + atomicAdd(&g_cur[d], 1);
        g_csr[pos] = src[e];
    }
}

// ---------------- cp.async double-buffered tensor-core GEMM ----------------
// out[n][j] = (sum_k A[n][k]*W[j][k] + bias[j]) [relu] [*dinv[n]], fp32 out.
// CTA 128x128, 256 thr, warps 4(M)x2(N). Pre-split bf16 planes, 3-pass hi/lo MMA.
#define SROWW 20                           // smem row stride (u32 words), conflict-free
#define STAGE_W   (4 * 128 * SROWW)        // words per stage (40KB)
#define STAGE_B   (STAGE_W * 4)
#define SMEM_DYN  (2 * STAGE_B)            // 80KB

__device__ __forceinline__ void mma16816(float* d, uint32_t a0, uint32_t a1,
                                         uint32_t a2, uint32_t a3,
                                         uint32_t b0, uint32_t b1) {
    asm volatile(
        "mma.sync.aligned.m16n8k16.row.col.f32.bf16.bf16.f32 "
        "{%0,%1,%2,%3}, {%4,%5,%6,%7}, {%8,%9}, {%0,%1,%2,%3};"
        : "+f"(d[0]), "+f"(d[1]), "+f"(d[2]), "+f"(d[3])
        : "r"(a0), "r"(a1), "r"(a2), "r"(a3), "r"(b0), "r"(b1));
}

template<int K, bool RELU_OUT, bool SCALE>
__global__ void __launch_bounds__(256)
k_gemm(const __nv_bfloat16* __restrict__ Ahi, const __nv_bfloat16* __restrict__ Alo,
       const __nv_bfloat16* __restrict__ Whi, const __nv_bfloat16* __restrict__ Wlo,
       const float* __restrict__ bias, float* __restrict__ Of)
{
    extern __shared__ __align__(16) char smem_dyn[];
    uint32_t* S = (uint32_t*)smem_dyn;
    const uint32_t sbase = (uint32_t)__cvta_generic_to_shared(smem_dyn);

    const int tid  = threadIdx.x;
    const int wid  = tid >> 5;
    const int lane = tid & 31;
    const int m_base = (wid >> 1) * 32;
    const int n_base = (wid & 1) * 64;
    const int n0   = blockIdx.x * 128;
    const int qr = lane >> 2;
    const int qj = lane & 3;

    constexpr int NCH = K / 32;

    // issue all cp.asyncs for chunk c into buffer buf
    auto issue = [&](int c, int buf) {
        #pragma unroll
        for (int it = 0; it < 8; it++) {
            int i     = it * 256 + tid;
            int plane = i >> 9;
            int r     = (i >> 2) & 127;
            int q     = i & 3;
            const __nv_bfloat16* P = (plane == 0) ? Ahi : (plane == 1) ? Alo
                                   : (plane == 2) ? Whi : Wlo;
            int rg;
            if (plane < 2) { int node = n0 + r; if (node >= N_NODES) node = N_NODES - 1; rg = node; }
            else           rg = r;
            const char* src = (const char*)P + ((size_t)rg * K + c * 32 + q * 8) * 2;
            uint32_t dstb = sbase + buf * STAGE_B + plane * (128 * SROWW * 4)
                          + r * (SROWW * 4) + q * 16;
            cp_async16(dstb, src);
        }
        cp_commit();
    };

    float acc[2][8][4];
    #pragma unroll
    for (int mt = 0; mt < 2; mt++)
        #pragma unroll
        for (int nt = 0; nt < 8; nt++)
            #pragma unroll
            for (int q = 0; q < 4; q++) acc[mt][nt][q] = 0.f;

    issue(0, 0);
    issue(1, 1);

    #pragma unroll
    for (int c = 0; c < NCH; c++) {
        if (c + 1 < NCH) cp_wait<1>(); else cp_wait<0>();
        __syncthreads();

        const int bw = (c & 1) * STAGE_W;
        uint32_t* sAh = S + bw;
        uint32_t* sAl = S + bw + 128 * SROWW;
        uint32_t* sWh = S + bw + 2 * 128 * SROWW;
        uint32_t* sWl = S + bw + 3 * 128 * SROWW;

        #pragma unroll
        for (int ks = 0; ks < 2; ks++) {
            const int kw = ks * 8 + qj;
            uint32_t ah[2][4], al[2][4];
            #pragma unroll
            for (int mt = 0; mt < 2; mt++) {
                int r0 = (m_base + mt * 16 + qr) * SROWW;
                int r1 = (m_base + mt * 16 + qr + 8) * SROWW;
                ah[mt][0] = sAh[r0 + kw];     ah[mt][1] = sAh[r1 + kw];
                ah[mt][2] = sAh[r0 + kw + 4]; ah[mt][3] = sAh[r1 + kw + 4];
                al[mt][0] = sAl[r0 + kw];     al[mt][1] = sAl[r1 + kw];
                al[mt][2] = sAl[r0 + kw + 4]; al[mt][3] = sAl[r1 + kw + 4];
            }
            #pragma unroll
            for (int nt = 0; nt < 8; nt++) {
                int nr = (n_base + nt * 8 + qr) * SROWW;
                uint32_t bh0 = sWh[nr + kw], bh1 = sWh[nr + kw + 4];
                uint32_t bl0 = sWl[nr + kw], bl1 = sWl[nr + kw + 4];
                #pragma unroll
                for (int mt = 0; mt < 2; mt++) {
                    mma16816(acc[mt][nt], ah[mt][0], ah[mt][1], ah[mt][2], ah[mt][3], bh0, bh1);
                    mma16816(acc[mt][nt], ah[mt][0], ah[mt][1], ah[mt][2], ah[mt][3], bl0, bl1);
                    mma16816(acc[mt][nt], al[mt][0], al[mt][1], al[mt][2], al[mt][3], bh0, bh1);
                }
            }
        }
        __syncthreads();
        if (c + 2 < NCH) issue(c + 2, c & 1);
    }

    // ---- epilogue: +bias, optional relu, optional *dinv[row], fp32 out ----
    #pragma unroll
    for (int mt = 0; mt < 2; mt++) {
        int r0 = n0 + m_base + mt * 16 + qr;
        int r1 = r0 + 8;
        float d0 = 1.f, d1 = 1.f;
        if (SCALE) {
            d0 = (r0 < N_NODES) ? g_dinv[r0] : 0.f;
            d1 = (r1 < N_NODES) ? g_dinv[r1] : 0.f;
        }
        #pragma unroll
        for (int nt = 0; nt < 8; nt++) {
            int col = n_base + nt * 8 + qj * 2;
            float b0 = bias[col], b1 = bias[col + 1];
            float vx0 = acc[mt][nt][0] + b0, vy0 = acc[mt][nt][1] + b1;
            float vx1 = acc[mt][nt][2] + b0, vy1 = acc[mt][nt][3] + b1;
            if (RELU_OUT) {
                vx0 = fmaxf(vx0, 0.f); vy0 = fmaxf(vy0, 0.f);
                vx1 = fmaxf(vx1, 0.f); vy1 = fmaxf(vy1, 0.f);
            }
            if (SCALE) { vx0 *= d0; vy0 *= d0; vx1 *= d1; vy1 *= d1; }
            if (r0 < N_NODES)
                *(float2*)(Of + (size_t)r0 * D_OUT + col) = make_float2(vx0, vy0);
            if (r1 < N_NODES)
                *(float2*)(Of + (size_t)r1 * D_OUT + col) = make_float2(vx1, vy1);
        }
    }
}

// ---------------- aggregation: fp32 prescaled in -> split bf16 planes out ----------------
// planes(n) = split( dinv[n] * ( x[n] + sum_{s in in(n)} x[s] ) )
__global__ void k_agg(const float* __restrict__ x,
                      __nv_bfloat16* __restrict__ ohi, __nv_bfloat16* __restrict__ olo)
{
    int gw   = (blockIdx.x * blockDim.x + threadIdx.x) >> 5;
    int lane = threadIdx.x & 31;
    if (gw >= N_NODES) return;

    const float4* x4 = (const float4*)x;
    float4 acc = x4[(size_t)gw * 32 + lane];           // self (prescaled)

    int b = g_off[gw], e = g_off[gw + 1];
    int i = b;
    for (; i + 4 <= e; i += 4) {
        int s0 = g_csr[i], s1 = g_csr[i+1], s2 = g_csr[i+2], s3 = g_csr[i+3];
        float4 v0 = x4[(size_t)s0 * 32 + lane];
        float4 v1 = x4[(size_t)s1 * 32 + lane];
        float4 v2 = x4[(size_t)s2 * 32 + lane];
        float4 v3 = x4[(size_t)s3 * 32 + lane];
        acc.x += (v0.x + v1.x) + (v2.x + v3.x);
        acc.y += (v0.y + v1.y) + (v2.y + v3.y);
        acc.z += (v0.z + v1.z) + (v2.z + v3.z);
        acc.w += (v0.w + v1.w) + (v2.w + v3.w);
    }
    for (; i < e; i++) {
        int s = g_csr[i];
        float4 v = x4[(size_t)s * 32 + lane];
        acc.x += v.x; acc.y += v.y; acc.z += v.z; acc.w += v.w;
    }

    float di = g_dinv[gw];
    uint2 hi, lo;
    split2(acc.x * di, acc.y * di, hi.x, lo.x);
    split2(acc.z * di, acc.w * di, hi.y, lo.y);
    ((uint2*)ohi)[(size_t)gw * 32 + lane] = hi;
    ((uint2*)olo)[(size_t)gw * 32 + lane] = lo;
}

// ---------------- launch ----------------
extern "C" void kernel_launch(void* const* d_in, const int* in_sizes, int n_in,
                              void* d_out, int out_size)
{
    const int*   tokens = (const int*)  d_in[0];
    const int*   eidx   = (const int*)  d_in[1];
    const float* embed  = (const float*)d_in[2];
    const float* Wn     = (const float*)d_in[3];
    const float* Wb     = (const float*)d_in[4];
    const float* w1     = (const float*)d_in[5];
    const float* b1     = (const float*)d_in[6];
    const float* w2     = (const float*)d_in[7];
    const float* b2     = (const float*)d_in[8];
    float* out = (float*)d_out;

    const int* src = eidx;
    const int* dst = eidx + N_EDGES;

    __nv_bfloat16 *Ehi, *Elo, *Zhi, *Zlo;
    __nv_bfloat16 *Wnh, *Wnl, *w1h, *w1l, *w2h, *w2l;
    float *xf, *hf;
    cudaGetSymbolAddress((void**)&Ehi, g_Ehi); cudaGetSymbolAddress((void**)&Elo, g_Elo);
    cudaGetSymbolAddress((void**)&Zhi, g_Zhi); cudaGetSymbolAddress((void**)&Zlo, g_Zlo);
    cudaGetSymbolAddress((void**)&xf,  g_xf);  cudaGetSymbolAddress((void**)&hf,  g_hf);
    cudaGetSymbolAddress((void**)&Wnh, g_Wnh); cudaGetSymbolAddress((void**)&Wnl, g_Wnl);
    cudaGetSymbolAddress((void**)&w1h, g_w1h); cudaGetSymbolAddress((void**)&w1l, g_w1l);
    cudaGetSymbolAddress((void**)&w2h, g_w2h); cudaGetSymbolAddress((void**)&w2l, g_w2l);

    cudaFuncSetAttribute(k_gemm<D_IN,  false, true >, cudaFuncAttributeMaxDynamicSharedMemorySize, SMEM_DYN);
    cudaFuncSetAttribute(k_gemm<D_OUT, true,  true >, cudaFuncAttributeMaxDynamicSharedMemorySize, SMEM_DYN);
    cudaFuncSetAttribute(k_gemm<D_OUT, false, false>, cudaFuncAttributeMaxDynamicSharedMemorySize, SMEM_DYN);

    const int NB_N = (N_NODES + 255) / 256;
    const int NB_E = (N_EDGES + 255) / 256;
    const int NB_G = (N_NODES + 127) / 128;
    const int NB_C = (N_NODES * 32 + 255) / 256;
    const int NB_P = (N_NODES * (D_IN / 4) + 255) / 256;

    // prepasses + structure
    k_presplit<<<NB_P, 256>>>(embed, tokens);
    k_splitw  <<<64,  256>>>(Wn, w1, w2);
    k_zero    <<<NB_N, 256>>>();
    k_count   <<<NB_E, 256>>>(dst);
    k_scan1   <<<NB_N, 256>>>();
    // GEMM1: x' = (E @ Wn^T + Wb) * dinv   (fp32 prescaled out)
    k_gemm<D_IN, false, true><<<NB_G, 256, SMEM_DYN>>>(Ehi, Elo, Wnh, Wnl, Wb, xf);
    k_scan2<<<1,    256>>>(NB_N);
    k_scan3<<<NB_N, 256>>>();
    k_fill <<<NB_E, 256>>>(src, dst);
    // agg1 -> Z planes
    k_agg<<<NB_C, 256>>>(xf, Zhi, Zlo);
    // GEMM2: h' = relu(Z @ w1^T + b1) * dinv
    k_gemm<D_OUT, true, true><<<NB_G, 256, SMEM_DYN>>>(Zhi, Zlo, w1h, w1l, b1, hf);
    // agg2 -> Z planes
    k_agg<<<NB_C, 256>>>(hf, Zhi, Zlo);
    // GEMM3: out = Z @ w2^T + b2
    k_gemm<D_OUT, false, false><<<NB_G, 256, SMEM_DYN>>>(Zhi, Zlo, w2h, w2l, b2, out);
}

// round 7
// speedup vs baseline: 1.4128x; 1.0391x over previous
#include <cuda_runtime.h>
#include <cuda_bf16.h>
#include <cuda_fp16.h>
#include <cstdint>

#define N_NODES 50000
#define N_EDGES 600000
#define D_IN    256
#define D_OUT   128

// ---------------- scratch (static device globals; no allocation) ----------------
__device__ __nv_bfloat16 g_Ehi[N_NODES * D_IN],  g_Elo[N_NODES * D_IN];   // gathered embed planes
__device__ __nv_bfloat16 g_Zhi[N_NODES * D_OUT], g_Zlo[N_NODES * D_OUT]; // agg output planes
__device__ __half g_xh[N_NODES * D_OUT];  // gemm1 out (prescaled*256, fp16)
__device__ __half g_hh[N_NODES * D_OUT];  // gemm2 out (relu, prescaled*256, fp16)
__device__ __nv_bfloat16 g_Wnh[128 * D_IN],  g_Wnl[128 * D_IN];
__device__ __nv_bfloat16 g_w1h[128 * D_OUT], g_w1l[128 * D_OUT];
__device__ __nv_bfloat16 g_w2h[128 * D_OUT], g_w2l[128 * D_OUT];

__device__ float g_dinv[N_NODES];
__device__ int   g_deg [N_NODES];
__device__ int   g_cur [N_NODES];
__device__ int   g_off [N_NODES + 1];
__device__ int   g_bsum [256];
__device__ int   g_bbase[256];
__device__ int   g_csr [N_EDGES];

// ---------------- helpers ----------------
__device__ __forceinline__ void split2(float x, float y, uint32_t& hi, uint32_t& lo) {
    __nv_bfloat162 h = __floats2bfloat162_rn(x, y);
    float2 hf = __bfloat1622float2(h);
    __nv_bfloat162 l = __floats2bfloat162_rn(x - hf.x, y - hf.y);
    hi = *(uint32_t*)&h; lo = *(uint32_t*)&l;
}
__device__ __forceinline__ void split4(float4 v, uint2& hi, uint2& lo) {
    split2(v.x, v.y, hi.x, lo.x);
    split2(v.z, v.w, hi.y, lo.y);
}
__device__ __forceinline__ void cp_async16(uint32_t saddr, const void* gaddr) {
    asm volatile("cp.async.cg.shared.global [%0], [%1], 16;" :: "r"(saddr), "l"(gaddr));
}
__device__ __forceinline__ void cp_commit() {
    asm volatile("cp.async.commit_group;" ::: "memory");
}
template<int N> __device__ __forceinline__ void cp_wait() {
    asm volatile("cp.async.wait_group %0;" :: "n"(N) : "memory");
}

// ---------------- pre-split kernels ----------------
// gather+split embed rows; also zeroes deg/cur (replaces k_zero)
__global__ void k_presplit(const float* __restrict__ embed, const int* __restrict__ tokens) {
    int t = blockIdx.x * 256 + threadIdx.x;
    if (t >= N_NODES * (D_IN / 4)) return;
    int row = t >> 6, q = t & 63;
    if (q == 0) { g_deg[row] = 0; g_cur[row] = 0; }
    int tok = __ldg(&tokens[row]);
    float4 v = ((const float4*)embed)[(size_t)tok * (D_IN / 4) + q];
    uint2 hi, lo; split4(v, hi, lo);
    ((uint2*)g_Ehi)[(size_t)row * (D_IN / 4) + q] = hi;
    ((uint2*)g_Elo)[(size_t)row * (D_IN / 4) + q] = lo;
}
__global__ void k_splitw(const float* __restrict__ Wn, const float* __restrict__ w1,
                         const float* __restrict__ w2) {
    int i = blockIdx.x * 256 + threadIdx.x;
    const float* src; __nv_bfloat16 *ph, *pl; int off;
    if (i < 8192)       { src = Wn; ph = g_Wnh; pl = g_Wnl; off = i; }
    else if (i < 12288) { src = w1; ph = g_w1h; pl = g_w1l; off = i - 8192; }
    else                { src = w2; ph = g_w2h; pl = g_w2l; off = i - 12288; }
    float4 v = ((const float4*)src)[off];
    uint2 hi, lo; split4(v, hi, lo);
    ((uint2*)ph)[off] = hi; ((uint2*)pl)[off] = lo;
}

// ---------------- graph-structure kernels ----------------
__global__ void k_count(const int* __restrict__ dst) {
    int e = blockIdx.x * blockDim.x + threadIdx.x;
    if (e < N_EDGES) atomicAdd(&g_deg[dst[e]], 1);
}
__global__ void k_scan1() {
    __shared__ int s[256];
    int i = blockIdx.x * 256 + threadIdx.x;
    int v = (i < N_NODES) ? g_deg[i] : 0;
    if (i < N_NODES) g_dinv[i] = rsqrtf((float)(v + 1));
    s[threadIdx.x] = v; __syncthreads();
    for (int d = 128; d > 0; d >>= 1) {
        if (threadIdx.x < d) s[threadIdx.x] += s[threadIdx.x + d];
        __syncthreads();
    }
    if (threadIdx.x == 0) g_bsum[blockIdx.x] = s[0];
}
__global__ void k_scan2(int nblk) {
    __shared__ int s[256];
    int t = threadIdx.x;
    int v = (t < nblk) ? g_bsum[t] : 0;
    s[t] = v; __syncthreads();
    for (int d = 1; d < 256; d <<= 1) {
        int u = (t >= d) ? s[t - d] : 0;
        __syncthreads(); s[t] += u; __syncthreads();
    }
    g_bbase[t] = s[t] - v;
    if (t == 0) g_off[N_NODES] = N_EDGES;
}
__global__ void k_scan3() {
    __shared__ int s[256];
    int t = threadIdx.x;
    int i = blockIdx.x * 256 + t;
    int v = (i < N_NODES) ? g_deg[i] : 0;
    s[t] = v; __syncthreads();
    for (int d = 1; d < 256; d <<= 1) {
        int u = (t >= d) ? s[t - d] : 0;
        __syncthreads(); s[t] += u; __syncthreads();
    }
    if (i < N_NODES) g_off[i] = g_bbase[blockIdx.x] + s[t] - v;
}
__global__ void k_fill(const int* __restrict__ src, const int* __restrict__ dst) {
    int e = blockIdx.x * blockDim.x + threadIdx.x;
    if (e < N_EDGES) {
        int d = dst[e];
        int pos = g_off[d] + atomicAdd(&g_cur[d], 1);
        g_csr[pos] = src[e];
    }
}

// ---------------- cp.async double-buffered tensor-core GEMM ----------------
// acc = A@W^T + bias; [relu]; out either fp16 (*dinv*256) or fp32.
#define SROWW 20
#define STAGE_W   (4 * 128 * SROWW)
#define STAGE_B   (STAGE_W * 4)
#define SMEM_DYN  (2 * STAGE_B)            // 80KB

__device__ __forceinline__ void mma16816(float* d, uint32_t a0, uint32_t a1,
                                         uint32_t a2, uint32_t a3,
                                         uint32_t b0, uint32_t b1) {
    asm volatile(
        "mma.sync.aligned.m16n8k16.row.col.f32.bf16.bf16.f32 "
        "{%0,%1,%2,%3}, {%4,%5,%6,%7}, {%8,%9}, {%0,%1,%2,%3};"
        : "+f"(d[0]), "+f"(d[1]), "+f"(d[2]), "+f"(d[3])
        : "r"(a0), "r"(a1), "r"(a2), "r"(a3), "r"(b0), "r"(b1));
}

template<int K, bool RELU_OUT, bool HALF_OUT>
__global__ void __launch_bounds__(256)
k_gemm(const __nv_bfloat16* __restrict__ Ahi, const __nv_bfloat16* __restrict__ Alo,
       const __nv_bfloat16* __restrict__ Whi, const __nv_bfloat16* __restrict__ Wlo,
       const float* __restrict__ bias, __half* __restrict__ Oh, float* __restrict__ Of)
{
    extern __shared__ __align__(16) char smem_dyn[];
    uint32_t* S = (uint32_t*)smem_dyn;
    const uint32_t sbase = (uint32_t)__cvta_generic_to_shared(smem_dyn);

    const int tid  = threadIdx.x;
    const int wid  = tid >> 5;
    const int lane = tid & 31;
    const int m_base = (wid >> 1) * 32;
    const int n_base = (wid & 1) * 64;
    const int n0   = blockIdx.x * 128;
    const int qr = lane >> 2;
    const int qj = lane & 3;

    constexpr int NCH = K / 32;

    auto issue = [&](int c, int buf) {
        #pragma unroll
        for (int it = 0; it < 8; it++) {
            int i     = it * 256 + tid;
            int plane = i >> 9;
            int r     = (i >> 2) & 127;
            int q     = i & 3;
            const __nv_bfloat16* P = (plane == 0) ? Ahi : (plane == 1) ? Alo
                                   : (plane == 2) ? Whi : Wlo;
            int rg;
            if (plane < 2) { int node = n0 + r; if (node >= N_NODES) node = N_NODES - 1; rg = node; }
            else           rg = r;
            const char* src = (const char*)P + ((size_t)rg * K + c * 32 + q * 8) * 2;
            uint32_t dstb = sbase + buf * STAGE_B + plane * (128 * SROWW * 4)
                          + r * (SROWW * 4) + q * 16;
            cp_async16(dstb, src);
        }
        cp_commit();
    };

    float acc[2][8][4];
    #pragma unroll
    for (int mt = 0; mt < 2; mt++)
        #pragma unroll
        for (int nt = 0; nt < 8; nt++)
            #pragma unroll
            for (int q = 0; q < 4; q++) acc[mt][nt][q] = 0.f;

    issue(0, 0);
    issue(1, 1);

    #pragma unroll
    for (int c = 0; c < NCH; c++) {
        if (c + 1 < NCH) cp_wait<1>(); else cp_wait<0>();
        __syncthreads();

        const int bw = (c & 1) * STAGE_W;
        uint32_t* sAh = S + bw;
        uint32_t* sAl = S + bw + 128 * SROWW;
        uint32_t* sWh = S + bw + 2 * 128 * SROWW;
        uint32_t* sWl = S + bw + 3 * 128 * SROWW;

        #pragma unroll
        for (int ks = 0; ks < 2; ks++) {
            const int kw = ks * 8 + qj;
            uint32_t ah[2][4], al[2][4];
            #pragma unroll
            for (int mt = 0; mt < 2; mt++) {
                int r0 = (m_base + mt * 16 + qr) * SROWW;
                int r1 = (m_base + mt * 16 + qr + 8) * SROWW;
                ah[mt][0] = sAh[r0 + kw];     ah[mt][1] = sAh[r1 + kw];
                ah[mt][2] = sAh[r0 + kw + 4]; ah[mt][3] = sAh[r1 + kw + 4];
                al[mt][0] = sAl[r0 + kw];     al[mt][1] = sAl[r1 + kw];
                al[mt][2] = sAl[r0 + kw + 4]; al[mt][3] = sAl[r1 + kw + 4];
            }
            #pragma unroll
            for (int nt = 0; nt < 8; nt++) {
                int nr = (n_base + nt * 8 + qr) * SROWW;
                uint32_t bh0 = sWh[nr + kw], bh1 = sWh[nr + kw + 4];
                uint32_t bl0 = sWl[nr + kw], bl1 = sWl[nr + kw + 4];
                #pragma unroll
                for (int mt = 0; mt < 2; mt++) {
                    mma16816(acc[mt][nt], ah[mt][0], ah[mt][1], ah[mt][2], ah[mt][3], bh0, bh1);
                    mma16816(acc[mt][nt], ah[mt][0], ah[mt][1], ah[mt][2], ah[mt][3], bl0, bl1);
                    mma16816(acc[mt][nt], al[mt][0], al[mt][1], al[mt][2], al[mt][3], bh0, bh1);
                }
            }
        }
        __syncthreads();
        if (c + 2 < NCH) issue(c + 2, c & 1);
    }

    // ---- epilogue ----
    #pragma unroll
    for (int mt = 0; mt < 2; mt++) {
        int r0 = n0 + m_base + mt * 16 + qr;
        int r1 = r0 + 8;
        float d0 = 1.f, d1 = 1.f;
        if (HALF_OUT) {   // prescale by dinv * 256 (exact pow2 lift out of subnormals)
            d0 = (r0 < N_NODES) ? g_dinv[r0] * 256.f : 0.f;
            d1 = (r1 < N_NODES) ? g_dinv[r1] * 256.f : 0.f;
        }
        #pragma unroll
        for (int nt = 0; nt < 8; nt++) {
            int col = n_base + nt * 8 + qj * 2;
            float b0 = bias[col], b1 = bias[col + 1];
            float vx0 = acc[mt][nt][0] + b0, vy0 = acc[mt][nt][1] + b1;
            float vx1 = acc[mt][nt][2] + b0, vy1 = acc[mt][nt][3] + b1;
            if (RELU_OUT) {
                vx0 = fmaxf(vx0, 0.f); vy0 = fmaxf(vy0, 0.f);
                vx1 = fmaxf(vx1, 0.f); vy1 = fmaxf(vy1, 0.f);
            }
            if (HALF_OUT) {
                if (r0 < N_NODES) {
                    __half2 h = __floats2half2_rn(vx0 * d0, vy0 * d0);
                    ((uint32_t*)Oh)[(size_t)r0 * 64 + (col >> 1)] = *(uint32_t*)&h;
                }
                if (r1 < N_NODES) {
                    __half2 h = __floats2half2_rn(vx1 * d1, vy1 * d1);
                    ((uint32_t*)Oh)[(size_t)r1 * 64 + (col >> 1)] = *(uint32_t*)&h;
                }
            } else {
                if (r0 < N_NODES)
                    *(float2*)(Of + (size_t)r0 * D_OUT + col) = make_float2(vx0, vy0);
                if (r1 < N_NODES)
                    *(float2*)(Of + (size_t)r1 * D_OUT + col) = make_float2(vx1, vy1);
            }
        }
    }
}

// ---------------- aggregation: fp16 prescaled(*256) in -> bf16 split planes out ----------------
// planes(n) = split( (dinv[n]/256) * ( x[n] + sum_{s in in(n)} x[s] ) )
__device__ __forceinline__ void hacc(float* a, uint2 v) {
    float2 p0 = __half22float2(*(__half2*)&v.x);
    float2 p1 = __half22float2(*(__half2*)&v.y);
    a[0] += p0.x; a[1] += p0.y; a[2] += p1.x; a[3] += p1.y;
}

__global__ void k_agg(const __half* __restrict__ x,
                      __nv_bfloat16* __restrict__ ohi, __nv_bfloat16* __restrict__ olo)
{
    int gw   = (blockIdx.x * blockDim.x + threadIdx.x) >> 5;
    int lane = threadIdx.x & 31;
    if (gw >= N_NODES) return;

    const uint2* x4 = (const uint2*)x;    // 4 halfs per lane
    float a[4] = {0.f, 0.f, 0.f, 0.f};
    hacc(a, x4[(size_t)gw * 32 + lane]);  // self

    int b = g_off[gw], e = g_off[gw + 1];
    int i = b;
    for (; i + 4 <= e; i += 4) {
        int s0 = g_csr[i], s1 = g_csr[i+1], s2 = g_csr[i+2], s3 = g_csr[i+3];
        uint2 v0 = x4[(size_t)s0 * 32 + lane];
        uint2 v1 = x4[(size_t)s1 * 32 + lane];
        uint2 v2 = x4[(size_t)s2 * 32 + lane];
        uint2 v3 = x4[(size_t)s3 * 32 + lane];
        hacc(a, v0); hacc(a, v1); hacc(a, v2); hacc(a, v3);
    }
    for (; i < e; i++) {
        int s = g_csr[i];
        hacc(a, x4[(size_t)s * 32 + lane]);
    }

    float di = g_dinv[gw] * (1.f / 256.f);
    uint2 hi, lo;
    split2(a[0] * di, a[1] * di, hi.x, lo.x);
    split2(a[2] * di, a[3] * di, hi.y, lo.y);
    ((uint2*)ohi)[(size_t)gw * 32 + lane] = hi;
    ((uint2*)olo)[(size_t)gw * 32 + lane] = lo;
}

// ---------------- launch ----------------
extern "C" void kernel_launch(void* const* d_in, const int* in_sizes, int n_in,
                              void* d_out, int out_size)
{
    const int*   tokens = (const int*)  d_in[0];
    const int*   eidx   = (const int*)  d_in[1];
    const float* embed  = (const float*)d_in[2];
    const float* Wn     = (const float*)d_in[3];
    const float* Wb     = (const float*)d_in[4];
    const float* w1     = (const float*)d_in[5];
    const float* b1     = (const float*)d_in[6];
    const float* w2     = (const float*)d_in[7];
    const float* b2     = (const float*)d_in[8];
    float* out = (float*)d_out;

    const int* src = eidx;
    const int* dst = eidx + N_EDGES;

    __nv_bfloat16 *Ehi, *Elo, *Zhi, *Zlo;
    __nv_bfloat16 *Wnh, *Wnl, *w1h, *w1l, *w2h, *w2l;
    __half *xh, *hh;
    cudaGetSymbolAddress((void**)&Ehi, g_Ehi); cudaGetSymbolAddress((void**)&Elo, g_Elo);
    cudaGetSymbolAddress((void**)&Zhi, g_Zhi); cudaGetSymbolAddress((void**)&Zlo, g_Zlo);
    cudaGetSymbolAddress((void**)&xh,  g_xh);  cudaGetSymbolAddress((void**)&hh,  g_hh);
    cudaGetSymbolAddress((void**)&Wnh, g_Wnh); cudaGetSymbolAddress((void**)&Wnl, g_Wnl);
    cudaGetSymbolAddress((void**)&w1h, g_w1h); cudaGetSymbolAddress((void**)&w1l, g_w1l);
    cudaGetSymbolAddress((void**)&w2h, g_w2h); cudaGetSymbolAddress((void**)&w2l, g_w2l);

    cudaFuncSetAttribute(k_gemm<D_IN,  false, true >, cudaFuncAttributeMaxDynamicSharedMemorySize, SMEM_DYN);
    cudaFuncSetAttribute(k_gemm<D_OUT, true,  true >, cudaFuncAttributeMaxDynamicSharedMemorySize, SMEM_DYN);
    cudaFuncSetAttribute(k_gemm<D_OUT, false, false>, cudaFuncAttributeMaxDynamicSharedMemorySize, SMEM_DYN);

    const int NB_N = (N_NODES + 255) / 256;
    const int NB_E = (N_EDGES + 255) / 256;
    const int NB_G = (N_NODES + 127) / 128;
    const int NB_C = (N_NODES * 32 + 255) / 256;
    const int NB_P = (N_NODES * (D_IN / 4) + 255) / 256;

    // prepasses + structure (presplit also zeroes deg/cur)
    k_presplit<<<NB_P, 256>>>(embed, tokens);
    k_splitw  <<<64,  256>>>(Wn, w1, w2);
    k_count   <<<NB_E, 256>>>(dst);
    k_scan1   <<<NB_N, 256>>>();
    // GEMM1: x' = (E @ Wn^T + Wb) * dinv * 256  (fp16 out)
    k_gemm<D_IN, false, true><<<NB_G, 256, SMEM_DYN>>>(Ehi, Elo, Wnh, Wnl, Wb, xh, nullptr);
    k_scan2<<<1,    256>>>(NB_N);
    k_scan3<<<NB_N, 256>>>();
    k_fill <<<NB_E, 256>>>(src, dst);
    // agg1 -> Z planes
    k_agg<<<NB_C, 256>>>(xh, Zhi, Zlo);
    // GEMM2: h' = relu(Z @ w1^T + b1) * dinv * 256  (fp16 out)
    k_gemm<D_OUT, true, true><<<NB_G, 256, SMEM_DYN>>>(Zhi, Zlo, w1h, w1l, b1, hh, nullptr);
    // agg2 -> Z planes
    k_agg<<<NB_C, 256>>>(hh, Zhi, Zlo);
    // GEMM3: out = Z @ w2^T + b2  (fp32 out)
    k_gemm<D_OUT, false, false><<<NB_G, 256, SMEM_DYN>>>(Zhi, Zlo, w2h, w2l, b2, nullptr, out);
}

// round 8
// speedup vs baseline: 1.6533x; 1.1702x over previous
#include <cuda_runtime.h>
#include <cuda_bf16.h>
#include <cuda_fp16.h>
#include <cstdint>

#define N_NODES 50000
#define N_EDGES 600000
#define D_IN    256
#define D_OUT   128

// ---------------- scratch (static device globals; no allocation) ----------------
__device__ __half g_E [N_NODES * D_IN];    // gathered embed, fp16
__device__ __half g_Z [N_NODES * D_OUT];   // agg output, fp16
__device__ __half g_xh[N_NODES * D_OUT];   // gemm1 out (prescaled*256, fp16)
__device__ __half g_hh[N_NODES * D_OUT];   // gemm2 out (relu, prescaled*256, fp16)
__device__ __half g_Wnh[128 * D_IN],  g_Wnl[128 * D_IN];    // W hi/lo fp16 planes
__device__ __half g_w1h[128 * D_OUT], g_w1l[128 * D_OUT];
__device__ __half g_w2h[128 * D_OUT], g_w2l[128 * D_OUT];

__device__ float g_dinv[N_NODES];
__device__ int   g_deg [N_NODES];
__device__ int   g_cur [N_NODES];
__device__ int   g_off [N_NODES + 1];
__device__ int   g_bsum [256];
__device__ int   g_bbase[256];
__device__ int   g_csr [N_EDGES];

// ---------------- helpers ----------------
__device__ __forceinline__ void wsplit2(float x, float y, uint32_t& hi, uint32_t& lo) {
    __half2 h = __floats2half2_rn(x, y);
    float2 hf = __half22float2(h);
    __half2 l = __floats2half2_rn(x - hf.x, y - hf.y);
    hi = *(uint32_t*)&h; lo = *(uint32_t*)&l;
}
__device__ __forceinline__ void cp_async16(uint32_t saddr, const void* gaddr) {
    asm volatile("cp.async.cg.shared.global [%0], [%1], 16;" :: "r"(saddr), "l"(gaddr));
}
__device__ __forceinline__ void cp_commit() {
    asm volatile("cp.async.commit_group;" ::: "memory");
}
template<int N> __device__ __forceinline__ void cp_wait() {
    asm volatile("cp.async.wait_group %0;" :: "n"(N) : "memory");
}

// ---------------- pre-pass kernels ----------------
// gather embed rows -> fp16; also zeroes deg/cur
__global__ void k_pregather(const float* __restrict__ embed, const int* __restrict__ tokens) {
    int t = blockIdx.x * 256 + threadIdx.x;
    if (t >= N_NODES * (D_IN / 4)) return;
    int row = t >> 6, q = t & 63;
    if (q == 0) { g_deg[row] = 0; g_cur[row] = 0; }
    int tok = __ldg(&tokens[row]);
    float4 v = ((const float4*)embed)[(size_t)tok * (D_IN / 4) + q];
    __half2 a = __floats2half2_rn(v.x, v.y);
    __half2 b = __floats2half2_rn(v.z, v.w);
    uint2 o = { *(uint32_t*)&a, *(uint32_t*)&b };
    ((uint2*)g_E)[(size_t)row * (D_IN / 4) + q] = o;
}
// split weights into fp16 hi/lo planes
__global__ void k_splitw(const float* __restrict__ Wn, const float* __restrict__ w1,
                         const float* __restrict__ w2) {
    int i = blockIdx.x * 256 + threadIdx.x;
    const float* src; __half *ph, *pl; int off;
    if (i < 8192)       { src = Wn; ph = g_Wnh; pl = g_Wnl; off = i; }
    else if (i < 12288) { src = w1; ph = g_w1h; pl = g_w1l; off = i - 8192; }
    else                { src = w2; ph = g_w2h; pl = g_w2l; off = i - 12288; }
    float4 v = ((const float4*)src)[off];
    uint2 hi, lo;
    wsplit2(v.x, v.y, hi.x, lo.x);
    wsplit2(v.z, v.w, hi.y, lo.y);
    ((uint2*)ph)[off] = hi; ((uint2*)pl)[off] = lo;
}

// ---------------- graph-structure kernels ----------------
__global__ void k_count(const int* __restrict__ dst) {
    int e = blockIdx.x * blockDim.x + threadIdx.x;
    if (e < N_EDGES) atomicAdd(&g_deg[dst[e]], 1);
}
__global__ void k_scan1() {
    __shared__ int s[256];
    int i = blockIdx.x * 256 + threadIdx.x;
    int v = (i < N_NODES) ? g_deg[i] : 0;
    if (i < N_NODES) g_dinv[i] = rsqrtf((float)(v + 1));
    s[threadIdx.x] = v; __syncthreads();
    for (int d = 128; d > 0; d >>= 1) {
        if (threadIdx.x < d) s[threadIdx.x] += s[threadIdx.x + d];
        __syncthreads();
    }
    if (threadIdx.x == 0) g_bsum[blockIdx.x] = s[0];
}
__global__ void k_scan2(int nblk) {
    __shared__ int s[256];
    int t = threadIdx.x;
    int v = (t < nblk) ? g_bsum[t] : 0;
    s[t] = v; __syncthreads();
    for (int d = 1; d < 256; d <<= 1) {
        int u = (t >= d) ? s[t - d] : 0;
        __syncthreads(); s[t] += u; __syncthreads();
    }
    g_bbase[t] = s[t] - v;
    if (t == 0) g_off[N_NODES] = N_EDGES;
}
__global__ void k_scan3() {
    __shared__ int s[256];
    int t = threadIdx.x;
    int i = blockIdx.x * 256 + t;
    int v = (i < N_NODES) ? g_deg[i] : 0;
    s[t] = v; __syncthreads();
    for (int d = 1; d < 256; d <<= 1) {
        int u = (t >= d) ? s[t - d] : 0;
        __syncthreads(); s[t] += u; __syncthreads();
    }
    if (i < N_NODES) g_off[i] = g_bbase[blockIdx.x] + s[t] - v;
}
__global__ void k_fill(const int* __restrict__ src, const int* __restrict__ dst) {
    int e = blockIdx.x * blockDim.x + threadIdx.x;
    if (e < N_EDGES) {
        int d = dst[e];
        int pos = g_off[d] + atomicAdd(&g_cur[d], 1);
        g_csr[pos] = src[e];
    }
}

// ---------------- cp.async double-buffered fp16 tensor-core GEMM ----------------
// acc = A@W^T + bias; [relu]; out fp16 (*dinv*256) or fp32. A single fp16 plane,
// W fp16 hi/lo, 2-pass MMA. CTA 128x128, 256 thr, warps 4(M)x2(N).
#define SROWW 20                           // smem row stride (u32 words)
#define STAGE_W   (3 * 128 * SROWW)        // 3 planes per stage
#define STAGE_B   (STAGE_W * 4)            // 30720 B
#define SMEM_DYN  (2 * STAGE_B)            // 61440 B

__device__ __forceinline__ void mma16816h(float* d, uint32_t a0, uint32_t a1,
                                          uint32_t a2, uint32_t a3,
                                          uint32_t b0, uint32_t b1) {
    asm volatile(
        "mma.sync.aligned.m16n8k16.row.col.f32.f16.f16.f32 "
        "{%0,%1,%2,%3}, {%4,%5,%6,%7}, {%8,%9}, {%0,%1,%2,%3};"
        : "+f"(d[0]), "+f"(d[1]), "+f"(d[2]), "+f"(d[3])
        : "r"(a0), "r"(a1), "r"(a2), "r"(a3), "r"(b0), "r"(b1));
}

template<int K, bool RELU_OUT, bool HALF_OUT>
__global__ void __launch_bounds__(256)
k_gemm(const __half* __restrict__ A,
       const __half* __restrict__ Whi, const __half* __restrict__ Wlo,
       const float* __restrict__ bias, __half* __restrict__ Oh, float* __restrict__ Of)
{
    extern __shared__ __align__(16) char smem_dyn[];
    uint32_t* S = (uint32_t*)smem_dyn;
    const uint32_t sbase = (uint32_t)__cvta_generic_to_shared(smem_dyn);

    const int tid  = threadIdx.x;
    const int wid  = tid >> 5;
    const int lane = tid & 31;
    const int m_base = (wid >> 1) * 32;
    const int n_base = (wid & 1) * 64;
    const int n0   = blockIdx.x * 128;
    const int qr = lane >> 2;
    const int qj = lane & 3;

    constexpr int NCH = K / 32;

    auto issue = [&](int c, int buf) {
        #pragma unroll
        for (int it = 0; it < 6; it++) {       // 3 planes x 128 rows x 4 uint4 = 1536
            int i     = it * 256 + tid;
            int plane = i >> 9;
            int r     = (i >> 2) & 127;
            int q     = i & 3;
            const __half* P = (plane == 0) ? A : (plane == 1) ? Whi : Wlo;
            int rg;
            if (plane == 0) { int node = n0 + r; if (node >= N_NODES) node = N_NODES - 1; rg = node; }
            else            rg = r;
            const char* src = (const char*)P + ((size_t)rg * K + c * 32 + q * 8) * 2;
            uint32_t dstb = sbase + buf * STAGE_B + plane * (128 * SROWW * 4)
                          + r * (SROWW * 4) + q * 16;
            cp_async16(dstb, src);
        }
        cp_commit();
    };

    float acc[2][8][4];
    #pragma unroll
    for (int mt = 0; mt < 2; mt++)
        #pragma unroll
        for (int nt = 0; nt < 8; nt++)
            #pragma unroll
            for (int q = 0; q < 4; q++) acc[mt][nt][q] = 0.f;

    issue(0, 0);
    issue(1, 1);

    #pragma unroll
    for (int c = 0; c < NCH; c++) {
        if (c + 1 < NCH) cp_wait<1>(); else cp_wait<0>();
        __syncthreads();

        const int bw = (c & 1) * STAGE_W;
        uint32_t* sA  = S + bw;
        uint32_t* sWh = S + bw + 128 * SROWW;
        uint32_t* sWl = S + bw + 2 * 128 * SROWW;

        #pragma unroll
        for (int ks = 0; ks < 2; ks++) {
            const int kw = ks * 8 + qj;
            uint32_t a[2][4];
            #pragma unroll
            for (int mt = 0; mt < 2; mt++) {
                int r0 = (m_base + mt * 16 + qr) * SROWW;
                int r1 = (m_base + mt * 16 + qr + 8) * SROWW;
                a[mt][0] = sA[r0 + kw];     a[mt][1] = sA[r1 + kw];
                a[mt][2] = sA[r0 + kw + 4]; a[mt][3] = sA[r1 + kw + 4];
            }
            #pragma unroll
            for (int nt = 0; nt < 8; nt++) {
                int nr = (n_base + nt * 8 + qr) * SROWW;
                uint32_t bh0 = sWh[nr + kw], bh1 = sWh[nr + kw + 4];
                uint32_t bl0 = sWl[nr + kw], bl1 = sWl[nr + kw + 4];
                #pragma unroll
                for (int mt = 0; mt < 2; mt++) {
                    mma16816h(acc[mt][nt], a[mt][0], a[mt][1], a[mt][2], a[mt][3], bh0, bh1);
                    mma16816h(acc[mt][nt], a[mt][0], a[mt][1], a[mt][2], a[mt][3], bl0, bl1);
                }
            }
        }
        __syncthreads();
        if (c + 2 < NCH) issue(c + 2, c & 1);
    }

    // ---- epilogue ----
    #pragma unroll
    for (int mt = 0; mt < 2; mt++) {
        int r0 = n0 + m_base + mt * 16 + qr;
        int r1 = r0 + 8;
        float d0 = 1.f, d1 = 1.f;
        if (HALF_OUT) {   // prescale by dinv * 256 (exact pow2 lift)
            d0 = (r0 < N_NODES) ? g_dinv[r0] * 256.f : 0.f;
            d1 = (r1 < N_NODES) ? g_dinv[r1] * 256.f : 0.f;
        }
        #pragma unroll
        for (int nt = 0; nt < 8; nt++) {
            int col = n_base + nt * 8 + qj * 2;
            float b0 = bias[col], b1 = bias[col + 1];
            float vx0 = acc[mt][nt][0] + b0, vy0 = acc[mt][nt][1] + b1;
            float vx1 = acc[mt][nt][2] + b0, vy1 = acc[mt][nt][3] + b1;
            if (RELU_OUT) {
                vx0 = fmaxf(vx0, 0.f); vy0 = fmaxf(vy0, 0.f);
                vx1 = fmaxf(vx1, 0.f); vy1 = fmaxf(vy1, 0.f);
            }
            if (HALF_OUT) {
                if (r0 < N_NODES) {
                    __half2 h = __floats2half2_rn(vx0 * d0, vy0 * d0);
                    ((uint32_t*)Oh)[(size_t)r0 * 64 + (col >> 1)] = *(uint32_t*)&h;
                }
                if (r1 < N_NODES) {
                    __half2 h = __floats2half2_rn(vx1 * d1, vy1 * d1);
                    ((uint32_t*)Oh)[(size_t)r1 * 64 + (col >> 1)] = *(uint32_t*)&h;
                }
            } else {
                if (r0 < N_NODES)
                    *(float2*)(Of + (size_t)r0 * D_OUT + col) = make_float2(vx0, vy0);
                if (r1 < N_NODES)
                    *(float2*)(Of + (size_t)r1 * D_OUT + col) = make_float2(vx1, vy1);
            }
        }
    }
}

// ---------------- aggregation: fp16 prescaled(*256) in -> fp16 out ----------------
// Z[n] = (dinv[n]/256) * ( x[n] + sum_{s in in(n)} x[s] )
__device__ __forceinline__ void hacc(float* a, uint2 v) {
    float2 p0 = __half22float2(*(__half2*)&v.x);
    float2 p1 = __half22float2(*(__half2*)&v.y);
    a[0] += p0.x; a[1] += p0.y; a[2] += p1.x; a[3] += p1.y;
}

__global__ void k_agg(const __half* __restrict__ x, __half* __restrict__ z)
{
    int gw   = (blockIdx.x * blockDim.x + threadIdx.x) >> 5;
    int lane = threadIdx.x & 31;
    if (gw >= N_NODES) return;

    const uint2* x4 = (const uint2*)x;    // 4 halfs per lane
    float a[4] = {0.f, 0.f, 0.f, 0.f};
    hacc(a, x4[(size_t)gw * 32 + lane]);  // self

    int b = g_off[gw], e = g_off[gw + 1];
    int i = b;
    for (; i + 4 <= e; i += 4) {
        int s0 = g_csr[i], s1 = g_csr[i+1], s2 = g_csr[i+2], s3 = g_csr[i+3];
        uint2 v0 = x4[(size_t)s0 * 32 + lane];
        uint2 v1 = x4[(size_t)s1 * 32 + lane];
        uint2 v2 = x4[(size_t)s2 * 32 + lane];
        uint2 v3 = x4[(size_t)s3 * 32 + lane];
        hacc(a, v0); hacc(a, v1); hacc(a, v2); hacc(a, v3);
    }
    for (; i < e; i++) {
        int s = g_csr[i];
        hacc(a, x4[(size_t)s * 32 + lane]);
    }

    float di = g_dinv[gw] * (1.f / 256.f);
    __half2 o0 = __floats2half2_rn(a[0] * di, a[1] * di);
    __half2 o1 = __floats2half2_rn(a[2] * di, a[3] * di);
    uint2 o = { *(uint32_t*)&o0, *(uint32_t*)&o1 };
    ((uint2*)z)[(size_t)gw * 32 + lane] = o;
}

// ---------------- launch ----------------
extern "C" void kernel_launch(void* const* d_in, const int* in_sizes, int n_in,
                              void* d_out, int out_size)
{
    const int*   tokens = (const int*)  d_in[0];
    const int*   eidx   = (const int*)  d_in[1];
    const float* embed  = (const float*)d_in[2];
    const float* Wn     = (const float*)d_in[3];
    const float* Wb     = (const float*)d_in[4];
    const float* w1     = (const float*)d_in[5];
    const float* b1     = (const float*)d_in[6];
    const float* w2     = (const float*)d_in[7];
    const float* b2     = (const float*)d_in[8];
    float* out = (float*)d_out;

    const int* src = eidx;
    const int* dst = eidx + N_EDGES;

    __half *E, *Z, *xh, *hh, *Wnh, *Wnl, *w1h, *w1l, *w2h, *w2l;
    cudaGetSymbolAddress((void**)&E,   g_E);   cudaGetSymbolAddress((void**)&Z,   g_Z);
    cudaGetSymbolAddress((void**)&xh,  g_xh);  cudaGetSymbolAddress((void**)&hh,  g_hh);
    cudaGetSymbolAddress((void**)&Wnh, g_Wnh); cudaGetSymbolAddress((void**)&Wnl, g_Wnl);
    cudaGetSymbolAddress((void**)&w1h, g_w1h); cudaGetSymbolAddress((void**)&w1l, g_w1l);
    cudaGetSymbolAddress((void**)&w2h, g_w2h); cudaGetSymbolAddress((void**)&w2l, g_w2l);

    cudaFuncSetAttribute(k_gemm<D_IN,  false, true >, cudaFuncAttributeMaxDynamicSharedMemorySize, SMEM_DYN);
    cudaFuncSetAttribute(k_gemm<D_OUT, true,  true >, cudaFuncAttributeMaxDynamicSharedMemorySize, SMEM_DYN);
    cudaFuncSetAttribute(k_gemm<D_OUT, false, false>, cudaFuncAttributeMaxDynamicSharedMemorySize, SMEM_DYN);

    const int NB_N = (N_NODES + 255) / 256;
    const int NB_E = (N_EDGES + 255) / 256;
    const int NB_G = (N_NODES + 127) / 128;
    const int NB_C = (N_NODES * 32 + 255) / 256;
    const int NB_P = (N_NODES * (D_IN / 4) + 255) / 256;

    // prepasses + structure (pregather also zeroes deg/cur)
    k_pregather<<<NB_P, 256>>>(embed, tokens);
    k_splitw   <<<64,  256>>>(Wn, w1, w2);
    k_count    <<<NB_E, 256>>>(dst);
    k_scan1    <<<NB_N, 256>>>();
    // GEMM1: x' = (E @ Wn^T + Wb) * dinv * 256  (fp16 out)
    k_gemm<D_IN, false, true><<<NB_G, 256, SMEM_DYN>>>(E, Wnh, Wnl, Wb, xh, nullptr);
    k_scan2<<<1,    256>>>(NB_N);
    k_scan3<<<NB_N, 256>>>();
    k_fill <<<NB_E, 256>>>(src, dst);
    // agg1 -> Z (fp16)
    k_agg<<<NB_C, 256>>>(xh, Z);
    // GEMM2: h' = relu(Z @ w1^T + b1) * dinv * 256  (fp16 out)
    k_gemm<D_OUT, true, true><<<NB_G, 256, SMEM_DYN>>>(Z, w1h, w1l, b1, hh, nullptr);
    // agg2 -> Z (fp16)
    k_agg<<<NB_C, 256>>>(hh, Z);
    // GEMM3: out = Z @ w2^T + b2  (fp32 out)
    k_gemm<D_OUT, false, false><<<NB_G, 256, SMEM_DYN>>>(Z, w2h, w2l, b2, nullptr, out);
}

// round 9
// speedup vs baseline: 1.7595x; 1.0642x over previous
#include <cuda_runtime.h>
#include <cuda_bf16.h>
#include <cuda_fp16.h>
#include <cstdint>

#define N_NODES 50000
#define N_EDGES 600000
#define D_IN    256
#define D_OUT   128

// ---------------- scratch (static device globals; no allocation) ----------------
__device__ __half g_E [N_NODES * D_IN];    // gathered embed, fp16
__device__ __half g_Z [N_NODES * D_OUT];   // agg output, fp16
__device__ __half g_xh[N_NODES * D_OUT];   // gemm1 out (prescaled*256, fp16)
__device__ __half g_hh[N_NODES * D_OUT];   // gemm2 out (relu, prescaled*256, fp16)
__device__ __half g_Wnh[128 * D_IN],  g_Wnl[128 * D_IN];    // W hi/lo fp16 planes
__device__ __half g_w1h[128 * D_OUT], g_w1l[128 * D_OUT];
__device__ __half g_w2h[128 * D_OUT], g_w2l[128 * D_OUT];

__device__ float g_dinv[N_NODES];
__device__ int   g_deg [N_NODES];
__device__ int   g_cur [N_NODES];
__device__ int   g_off [N_NODES + 1];
__device__ int   g_bsum [256];
__device__ int   g_bbase[256];
__device__ int   g_csr [N_EDGES];

// ---------------- helpers ----------------
__device__ __forceinline__ void wsplit2(float x, float y, uint32_t& hi, uint32_t& lo) {
    __half2 h = __floats2half2_rn(x, y);
    float2 hf = __half22float2(h);
    __half2 l = __floats2half2_rn(x - hf.x, y - hf.y);
    hi = *(uint32_t*)&h; lo = *(uint32_t*)&l;
}
__device__ __forceinline__ void cp_async16(uint32_t saddr, const void* gaddr) {
    asm volatile("cp.async.cg.shared.global [%0], [%1], 16;" :: "r"(saddr), "l"(gaddr));
}
__device__ __forceinline__ void cp_commit() {
    asm volatile("cp.async.commit_group;" ::: "memory");
}
template<int N> __device__ __forceinline__ void cp_wait() {
    asm volatile("cp.async.wait_group %0;" :: "n"(N) : "memory");
}

// ---------------- pre-pass kernels ----------------
__global__ void k_pregather(const float* __restrict__ embed, const int* __restrict__ tokens) {
    int t = blockIdx.x * 256 + threadIdx.x;
    if (t >= N_NODES * (D_IN / 4)) return;
    int row = t >> 6, q = t & 63;
    int tok = __ldg(&tokens[row]);
    float4 v = ((const float4*)embed)[(size_t)tok * (D_IN / 4) + q];
    __half2 a = __floats2half2_rn(v.x, v.y);
    __half2 b = __floats2half2_rn(v.z, v.w);
    uint2 o = { *(uint32_t*)&a, *(uint32_t*)&b };
    ((uint2*)g_E)[(size_t)row * (D_IN / 4) + q] = o;
}
__global__ void k_splitw(const float* __restrict__ Wn, const float* __restrict__ w1,
                         const float* __restrict__ w2) {
    int i = blockIdx.x * 256 + threadIdx.x;
    const float* src; __half *ph, *pl; int off;
    if (i < 8192)       { src = Wn; ph = g_Wnh; pl = g_Wnl; off = i; }
    else if (i < 12288) { src = w1; ph = g_w1h; pl = g_w1l; off = i - 8192; }
    else                { src = w2; ph = g_w2h; pl = g_w2l; off = i - 12288; }
    float4 v = ((const float4*)src)[off];
    uint2 hi, lo;
    wsplit2(v.x, v.y, hi.x, lo.x);
    wsplit2(v.z, v.w, hi.y, lo.y);
    ((uint2*)ph)[off] = hi; ((uint2*)pl)[off] = lo;
}

// ---------------- graph-structure kernels ----------------
__global__ void k_zero() {
    int i = blockIdx.x * blockDim.x + threadIdx.x;
    if (i < N_NODES) { g_deg[i] = 0; g_cur[i] = 0; }
}
__global__ void k_count(const int* __restrict__ dst) {
    int e = blockIdx.x * blockDim.x + threadIdx.x;
    if (e < N_EDGES) atomicAdd(&g_deg[dst[e]], 1);
}
__global__ void k_scan1() {
    __shared__ int s[256];
    int i = blockIdx.x * 256 + threadIdx.x;
    int v = (i < N_NODES) ? g_deg[i] : 0;
    if (i < N_NODES) g_dinv[i] = rsqrtf((float)(v + 1));
    s[threadIdx.x] = v; __syncthreads();
    for (int d = 128; d > 0; d >>= 1) {
        if (threadIdx.x < d) s[threadIdx.x] += s[threadIdx.x + d];
        __syncthreads();
    }
    if (threadIdx.x == 0) g_bsum[blockIdx.x] = s[0];
}
__global__ void k_scan2(int nblk) {
    __shared__ int s[256];
    int t = threadIdx.x;
    int v = (t < nblk) ? g_bsum[t] : 0;
    s[t] = v; __syncthreads();
    for (int d = 1; d < 256; d <<= 1) {
        int u = (t >= d) ? s[t - d] : 0;
        __syncthreads(); s[t] += u; __syncthreads();
    }
    g_bbase[t] = s[t] - v;
    if (t == 0) g_off[N_NODES] = N_EDGES;
}
__global__ void k_scan3() {
    __shared__ int s[256];
    int t = threadIdx.x;
    int i = blockIdx.x * 256 + t;
    int v = (i < N_NODES) ? g_deg[i] : 0;
    s[t] = v; __syncthreads();
    for (int d = 1; d < 256; d <<= 1) {
        int u = (t >= d) ? s[t - d] : 0;
        __syncthreads(); s[t] += u; __syncthreads();
    }
    if (i < N_NODES) g_off[i] = g_bbase[blockIdx.x] + s[t] - v;
}
__global__ void k_fill(const int* __restrict__ src, const int* __restrict__ dst) {
    int e = blockIdx.x * blockDim.x + threadIdx.x;
    if (e < N_EDGES) {
        int d = dst[e];
        int pos = g_off[d] + atomicAdd(&g_cur[d], 1);
        g_csr[pos] = src[e];
    }
}

// ---------------- cp.async double-buffered fp16 tensor-core GEMM ----------------
#define SROWW 20
#define STAGE_W   (3 * 128 * SROWW)
#define STAGE_B   (STAGE_W * 4)
#define SMEM_DYN  (2 * STAGE_B)            // 61440 B

__device__ __forceinline__ void mma16816h(float* d, uint32_t a0, uint32_t a1,
                                          uint32_t a2, uint32_t a3,
                                          uint32_t b0, uint32_t b1) {
    asm volatile(
        "mma.sync.aligned.m16n8k16.row.col.f32.f16.f16.f32 "
        "{%0,%1,%2,%3}, {%4,%5,%6,%7}, {%8,%9}, {%0,%1,%2,%3};"
        : "+f"(d[0]), "+f"(d[1]), "+f"(d[2]), "+f"(d[3])
        : "r"(a0), "r"(a1), "r"(a2), "r"(a3), "r"(b0), "r"(b1));
}

template<int K, bool RELU_OUT, bool HALF_OUT>
__global__ void __launch_bounds__(256)
k_gemm(const __half* __restrict__ A,
       const __half* __restrict__ Whi, const __half* __restrict__ Wlo,
       const float* __restrict__ bias, __half* __restrict__ Oh, float* __restrict__ Of)
{
    extern __shared__ __align__(16) char smem_dyn[];
    uint32_t* S = (uint32_t*)smem_dyn;
    const uint32_t sbase = (uint32_t)__cvta_generic_to_shared(smem_dyn);

    const int tid  = threadIdx.x;
    const int wid  = tid >> 5;
    const int lane = tid & 31;
    const int m_base = (wid >> 1) * 32;
    const int n_base = (wid & 1) * 64;
    const int n0   = blockIdx.x * 128;
    const int qr = lane >> 2;
    const int qj = lane & 3;

    constexpr int NCH = K / 32;

    auto issue = [&](int c, int buf) {
        #pragma unroll
        for (int it = 0; it < 6; it++) {
            int i     = it * 256 + tid;
            int plane = i >> 9;
            int r     = (i >> 2) & 127;
            int q     = i & 3;
            const __half* P = (plane == 0) ? A : (plane == 1) ? Whi : Wlo;
            int rg;
            if (plane == 0) { int node = n0 + r; if (node >= N_NODES) node = N_NODES - 1; rg = node; }
            else            rg = r;
            const char* src = (const char*)P + ((size_t)rg * K + c * 32 + q * 8) * 2;
            uint32_t dstb = sbase + buf * STAGE_B + plane * (128 * SROWW * 4)
                          + r * (SROWW * 4) + q * 16;
            cp_async16(dstb, src);
        }
        cp_commit();
    };

    float acc[2][8][4];
    #pragma unroll
    for (int mt = 0; mt < 2; mt++)
        #pragma unroll
        for (int nt = 0; nt < 8; nt++)
            #pragma unroll
            for (int q = 0; q < 4; q++) acc[mt][nt][q] = 0.f;

    issue(0, 0);
    issue(1, 1);

    #pragma unroll
    for (int c = 0; c < NCH; c++) {
        if (c + 1 < NCH) cp_wait<1>(); else cp_wait<0>();
        __syncthreads();

        const int bw = (c & 1) * STAGE_W;
        uint32_t* sA  = S + bw;
        uint32_t* sWh = S + bw + 128 * SROWW;
        uint32_t* sWl = S + bw + 2 * 128 * SROWW;

        #pragma unroll
        for (int ks = 0; ks < 2; ks++) {
            const int kw = ks * 8 + qj;
            uint32_t a[2][4];
            #pragma unroll
            for (int mt = 0; mt < 2; mt++) {
                int r0 = (m_base + mt * 16 + qr) * SROWW;
                int r1 = (m_base + mt * 16 + qr + 8) * SROWW;
                a[mt][0] = sA[r0 + kw];     a[mt][1] = sA[r1 + kw];
                a[mt][2] = sA[r0 + kw + 4]; a[mt][3] = sA[r1 + kw + 4];
            }
            #pragma unroll
            for (int nt = 0; nt < 8; nt++) {
                int nr = (n_base + nt * 8 + qr) * SROWW;
                uint32_t bh0 = sWh[nr + kw], bh1 = sWh[nr + kw + 4];
                uint32_t bl0 = sWl[nr + kw], bl1 = sWl[nr + kw + 4];
                #pragma unroll
                for (int mt = 0; mt < 2; mt++) {
                    mma16816h(acc[mt][nt], a[mt][0], a[mt][1], a[mt][2], a[mt][3], bh0, bh1);
                    mma16816h(acc[mt][nt], a[mt][0], a[mt][1], a[mt][2], a[mt][3], bl0, bl1);
                }
            }
        }
        __syncthreads();
        if (c + 2 < NCH) issue(c + 2, c & 1);
    }

    // ---- epilogue ----
    #pragma unroll
    for (int mt = 0; mt < 2; mt++) {
        int r0 = n0 + m_base + mt * 16 + qr;
        int r1 = r0 + 8;
        float d0 = 1.f, d1 = 1.f;
        if (HALF_OUT) {
            d0 = (r0 < N_NODES) ? g_dinv[r0] * 256.f : 0.f;
            d1 = (r1 < N_NODES) ? g_dinv[r1] * 256.f : 0.f;
        }
        #pragma unroll
        for (int nt = 0; nt < 8; nt++) {
            int col = n_base + nt * 8 + qj * 2;
            float b0 = bias[col], b1 = bias[col + 1];
            float vx0 = acc[mt][nt][0] + b0, vy0 = acc[mt][nt][1] + b1;
            float vx1 = acc[mt][nt][2] + b0, vy1 = acc[mt][nt][3] + b1;
            if (RELU_OUT) {
                vx0 = fmaxf(vx0, 0.f); vy0 = fmaxf(vy0, 0.f);
                vx1 = fmaxf(vx1, 0.f); vy1 = fmaxf(vy1, 0.f);
            }
            if (HALF_OUT) {
                if (r0 < N_NODES) {
                    __half2 h = __floats2half2_rn(vx0 * d0, vy0 * d0);
                    ((uint32_t*)Oh)[(size_t)r0 * 64 + (col >> 1)] = *(uint32_t*)&h;
                }
                if (r1 < N_NODES) {
                    __half2 h = __floats2half2_rn(vx1 * d1, vy1 * d1);
                    ((uint32_t*)Oh)[(size_t)r1 * 64 + (col >> 1)] = *(uint32_t*)&h;
                }
            } else {
                if (r0 < N_NODES)
                    *(float2*)(Of + (size_t)r0 * D_OUT + col) = make_float2(vx0, vy0);
                if (r1 < N_NODES)
                    *(float2*)(Of + (size_t)r1 * D_OUT + col) = make_float2(vx1, vy1);
            }
        }
    }
}

// ---------------- aggregation: fp16 prescaled(*256) in -> fp16 out ----------------
__device__ __forceinline__ void hacc(float* a, uint2 v) {
    float2 p0 = __half22float2(*(__half2*)&v.x);
    float2 p1 = __half22float2(*(__half2*)&v.y);
    a[0] += p0.x; a[1] += p0.y; a[2] += p1.x; a[3] += p1.y;
}

__global__ void k_agg(const __half* __restrict__ x, __half* __restrict__ z)
{
    int gw   = (blockIdx.x * blockDim.x + threadIdx.x) >> 5;
    int lane = threadIdx.x & 31;
    if (gw >= N_NODES) return;

    const uint2* x4 = (const uint2*)x;
    float a[4] = {0.f, 0.f, 0.f, 0.f};
    hacc(a, x4[(size_t)gw * 32 + lane]);  // self

    int b = g_off[gw], e = g_off[gw + 1];
    int i = b;
    for (; i + 4 <= e; i += 4) {
        int s0 = g_csr[i], s1 = g_csr[i+1], s2 = g_csr[i+2], s3 = g_csr[i+3];
        uint2 v0 = x4[(size_t)s0 * 32 + lane];
        uint2 v1 = x4[(size_t)s1 * 32 + lane];
        uint2 v2 = x4[(size_t)s2 * 32 + lane];
        uint2 v3 = x4[(size_t)s3 * 32 + lane];
        hacc(a, v0); hacc(a, v1); hacc(a, v2); hacc(a, v3);
    }
    for (; i < e; i++) {
        int s = g_csr[i];
        hacc(a, x4[(size_t)s * 32 + lane]);
    }

    float di = g_dinv[gw] * (1.f / 256.f);
    __half2 o0 = __floats2half2_rn(a[0] * di, a[1] * di);
    __half2 o1 = __floats2half2_rn(a[2] * di, a[3] * di);
    uint2 o = { *(uint32_t*)&o0, *(uint32_t*)&o1 };
    ((uint2*)z)[(size_t)gw * 32 + lane] = o;
}

// ---------------- launch (forked-stream capture: structure || compute) ----------------
extern "C" void kernel_launch(void* const* d_in, const int* in_sizes, int n_in,
                              void* d_out, int out_size)
{
    const int*   tokens = (const int*)  d_in[0];
    const int*   eidx   = (const int*)  d_in[1];
    const float* embed  = (const float*)d_in[2];
    const float* Wn     = (const float*)d_in[3];
    const float* Wb     = (const float*)d_in[4];
    const float* w1     = (const float*)d_in[5];
    const float* b1     = (const float*)d_in[6];
    const float* w2     = (const float*)d_in[7];
    const float* b2     = (const float*)d_in[8];
    float* out = (float*)d_out;

    const int* src = eidx;
    const int* dst = eidx + N_EDGES;

    __half *E, *Z, *xh, *hh, *Wnh, *Wnl, *w1h, *w1l, *w2h, *w2l;
    cudaGetSymbolAddress((void**)&E,   g_E);   cudaGetSymbolAddress((void**)&Z,   g_Z);
    cudaGetSymbolAddress((void**)&xh,  g_xh);  cudaGetSymbolAddress((void**)&hh,  g_hh);
    cudaGetSymbolAddress((void**)&Wnh, g_Wnh); cudaGetSymbolAddress((void**)&Wnl, g_Wnl);
    cudaGetSymbolAddress((void**)&w1h, g_w1h); cudaGetSymbolAddress((void**)&w1l, g_w1l);
    cudaGetSymbolAddress((void**)&w2h, g_w2h); cudaGetSymbolAddress((void**)&w2l, g_w2l);

    cudaFuncSetAttribute(k_gemm<D_IN,  false, true >, cudaFuncAttributeMaxDynamicSharedMemorySize, SMEM_DYN);
    cudaFuncSetAttribute(k_gemm<D_OUT, true,  true >, cudaFuncAttributeMaxDynamicSharedMemorySize, SMEM_DYN);
    cudaFuncSetAttribute(k_gemm<D_OUT, false, false>, cudaFuncAttributeMaxDynamicSharedMemorySize, SMEM_DYN);

    // one-time side-stream + events (created on the uncaptured correctness call)
    static cudaStream_t sB = nullptr;
    static cudaEvent_t evFork = nullptr, evDinv = nullptr, evCsr = nullptr;
    if (!sB) {
        cudaStreamCreateWithFlags(&sB, cudaStreamNonBlocking);
        cudaEventCreateWithFlags(&evFork, cudaEventDisableTiming);
        cudaEventCreateWithFlags(&evDinv, cudaEventDisableTiming);
        cudaEventCreateWithFlags(&evCsr,  cudaEventDisableTiming);
    }

    const int NB_N = (N_NODES + 255) / 256;
    const int NB_E = (N_EDGES + 255) / 256;
    const int NB_G = (N_NODES + 127) / 128;
    const int NB_C = (N_NODES * 32 + 255) / 256;
    const int NB_P = (N_NODES * (D_IN / 4) + 255) / 256;

    // fork stream B off the capture stream
    cudaEventRecord(evFork, 0);
    cudaStreamWaitEvent(sB, evFork, 0);

    // stream B: graph structure
    k_zero <<<NB_N, 256, 0, sB>>>();
    k_count<<<NB_E, 256, 0, sB>>>(dst);
    k_scan1<<<NB_N, 256, 0, sB>>>();
    cudaEventRecord(evDinv, sB);               // dinv ready
    k_scan2<<<1,    256, 0, sB>>>(NB_N);
    k_scan3<<<NB_N, 256, 0, sB>>>();
    k_fill <<<NB_E, 256, 0, sB>>>(src, dst);
    cudaEventRecord(evCsr, sB);                // CSR ready

    // stream 0: operand prep
    k_pregather<<<NB_P, 256>>>(embed, tokens);
    k_splitw   <<<64,  256>>>(Wn, w1, w2);

    // GEMM1 needs E/W planes (stream 0) + dinv (event)
    cudaStreamWaitEvent(0, evDinv, 0);
    k_gemm<D_IN, false, true><<<NB_G, 256, SMEM_DYN>>>(E, Wnh, Wnl, Wb, xh, nullptr);

    // agg1 needs GEMM1 (stream 0) + CSR (event)
    cudaStreamWaitEvent(0, evCsr, 0);
    k_agg<<<NB_C, 256>>>(xh, Z);
    k_gemm<D_OUT, true, true><<<NB_G, 256, SMEM_DYN>>>(Z, w1h, w1l, b1, hh, nullptr);
    k_agg<<<NB_C, 256>>>(hh, Z);
    k_gemm<D_OUT, false, false><<<NB_G, 256, SMEM_DYN>>>(Z, w2h, w2l, b2, nullptr, out);
}